// round 13
// baseline (speedup 1.0000x reference)
#include <cuda_runtime.h>

// h_t = alpha_t * h_{t-1} + x_t over axis 1 of float32 [4, 8192, 1024].
// Persistent scan (R6 skeleton): one block per chain, 32 chunks of 256 rows,
// register double-buffered prefetch, one __syncthreads per chunk.
// R13: mixed-width d-tiles to cover ALL 148 SMs. Each batch's 1024 d-lanes
// split into 37 tiles (36 x 28-wide + 1 x 16-wide) -> grid = 148, one block
// per SM. Makespan scales with the widest tile: 28/32 of R6. Idle lanes load
// a clamped duplicate address (no extra traffic) and are predicated off for
// stores.

#define B_      4
#define S_      8192
#define D_      1024
#define R_      16                    // s-steps per thread per chunk
#define SUBS_   16                    // warps per block
#define TPB_    512
#define CHUNK_  (R_ * SUBS_)          // 256 s-steps per chunk
#define ITERS_  (S_ / CHUNK_)         // 32 chunks per chain
#define TILES_  37                    // d-tiles per batch
#define WIDE_   28                    // width of tiles 0..35
#define GRID_   (B_ * TILES_)         // 148 blocks = 148 SMs

// One chunk body. CUR/NXT are compile-time buffer indices (ping-pong).
// Prefetch LDGs for chunk K+1 are issued BEFORE the barrier/fold/stores of
// chunk K, so DRAM streams through the serial section.
#define BODY(CUR, NXT, K)                                                     \
    {                                                                         \
        const size_t nbase = base + (size_t)CHUNK_ * D_;                      \
        if ((K) + 1 < ITERS_) {                                               \
            _Pragma("unroll")                                                 \
            for (int r = 0; r < R_; r++)                                      \
                A[NXT][r] = __ldcg(alpha + nbase + (size_t)r * D_);           \
            _Pragma("unroll")                                                 \
            for (int r = 0; r < R_; r++)                                      \
                X[NXT][r] = __ldcg(x + nbase + (size_t)r * D_);               \
        }                                                                     \
        float P = 1.0f, L = 0.0f;                                             \
        _Pragma("unroll")                                                     \
        for (int r = 0; r < R_; r++) {                                        \
            L = fmaf(A[CUR][r], L, X[CUR][r]);                                \
            P = P * A[CUR][r];                                                \
            A[CUR][r] = P;   /* per-step cumprod  */                          \
            X[CUR][r] = L;   /* per-step local scan */                        \
        }                                                                     \
        sp[CUR][w][lane] = P;                                                 \
        sl[CUR][w][lane] = L;                                                 \
        __syncthreads();                                                      \
        /* every warp folds all 16 aggregates: h0 = prefix before own warp, */\
        /* acc = full fold -> next chunk's carry (identical in all warps).  */\
        float acc = cin, h0 = cin;                                            \
        _Pragma("unroll")                                                     \
        for (int w2 = 0; w2 < SUBS_; w2++) {                                  \
            if (w2 == w) h0 = acc;                                            \
            acc = fmaf(sp[CUR][w2][lane], acc, sl[CUR][w2][lane]);            \
        }                                                                     \
        cin = acc;                                                            \
        _Pragma("unroll")                                                     \
        for (int r = 0; r < R_; r++) {                                        \
            float o = fmaf(A[CUR][r], h0, X[CUR][r]);                         \
            if (act) __stcs(out + base + (size_t)r * D_, o);                  \
        }                                                                     \
        base = nbase;                                                         \
    }

__global__ __launch_bounds__(TPB_, 1) void scan_kernel(const float* __restrict__ x,
                                                       const float* __restrict__ alpha,
                                                       float* __restrict__ out) {
    // Double-buffered per-warp aggregates: one __syncthreads per chunk is
    // race-free (sync at k+1 separates read(k) from write(k+2), same buffer).
    __shared__ float sp[2][SUBS_][32];
    __shared__ float sl[2][SUBS_][32];

    const int lane = threadIdx.x & 31;
    const int w    = threadIdx.x >> 5;    // warp = s-subchunk within chunk
    const int bid  = blockIdx.x;
    const int b    = bid / TILES_;        // batch
    const int t    = bid % TILES_;        // d-tile within batch
    const int wid  = (t == TILES_ - 1) ? (D_ - WIDE_ * (TILES_ - 1)) : WIDE_;
    const int d0   = (t == TILES_ - 1) ? WIDE_ * (TILES_ - 1) : WIDE_ * t;
    const bool act = lane < wid;
    // Idle lanes load a clamped (duplicate) address: valid memory, broadcast
    // within the already-touched sectors, zero extra DRAM traffic.
    const int d    = d0 + (act ? lane : 0);

    size_t base = ((size_t)b * S_ + (size_t)w * R_) * (size_t)D_ + d;

    float A[2][R_], X[2][R_];
    float cin = 0.0f;

    // Preload chunk 0.
#pragma unroll
    for (int r = 0; r < R_; r++) A[0][r] = __ldcg(alpha + base + (size_t)r * D_);
#pragma unroll
    for (int r = 0; r < R_; r++) X[0][r] = __ldcg(x + base + (size_t)r * D_);

#pragma unroll 1
    for (int k = 0; k < ITERS_; k += 2) {
        BODY(0, 1, k)
        BODY(1, 0, k + 1)
    }
}

extern "C" void kernel_launch(void* const* d_in, const int* in_sizes, int n_in,
                              void* d_out, int out_size) {
    const float* xp = (const float*)d_in[0];
    const float* ap = (const float*)d_in[1];
    float* op = (float*)d_out;

    scan_kernel<<<GRID_, TPB_>>>(xp, ap, op);
}

// round 14
// speedup vs baseline: 1.0123x; 1.0123x over previous
#include <cuda_runtime.h>

// h_t = alpha_t * h_{t-1} + x_t over axis 1 of float32 [4, 8192, 1024].
// Persistent scan: one block per (batch, 32-wide d-tile) chain = 128 blocks.
// R14: NO block barrier in the main loop. Warp w owns row-chunks
// c = w + 16*j (16 rows each, j = 0..31) and carries flow warp-to-warp
// through a 32-slot smem token ring (32 floats + monotone counter flag per
// slot). Each warp double-buffers its next chunk's loads in registers before
// touching the ring, so DRAM streams continuously while the lightweight
// carry chain (1 FMA + ~60cyc smem handoff per 16 rows) runs underneath.

#define B_      4
#define S_      8192
#define D_      1024
#define NW_     16                    // warps per block
#define TPB_    (NW_ * 32)
#define RC_     16                    // rows per chunk (= rows per thread)
#define NCH_    (S_ / RC_)            // 512 chunks per chain
#define JITERS_ (NCH_ / NW_)          // 32 chunks per warp
#define RING_   32                    // carry ring slots (= 2 warp rounds)
#define LG_     (B_ * (D_ / 32))      // 128 chains = 128 blocks

// One per-warp chunk body. CUR/NXT: register ping-pong. J is a runtime int.
// Order: issue loads for chunk J+1, local scan of J, ring wait (carry in),
// emit carry for J+1 (chain advances ASAP), then stores of J.
#define BODY(CUR, NXT, J)                                                     \
    {                                                                         \
        const size_t nbase = base + (size_t)(NW_ * RC_) * D_;                 \
        if ((J) + 1 < JITERS_) {                                              \
            _Pragma("unroll")                                                 \
            for (int r = 0; r < RC_; r++)                                     \
                A[NXT][r] = __ldcg(alpha + nbase + (size_t)r * D_);           \
            _Pragma("unroll")                                                 \
            for (int r = 0; r < RC_; r++)                                     \
                X[NXT][r] = __ldcg(x + nbase + (size_t)r * D_);               \
        }                                                                     \
        float P = 1.0f, L = 0.0f;                                             \
        _Pragma("unroll")                                                     \
        for (int r = 0; r < RC_; r++) {                                       \
            L = fmaf(A[CUR][r], L, X[CUR][r]);                                \
            P = P * A[CUR][r];                                                \
            A[CUR][r] = P;   /* per-step cumprod    */                        \
            X[CUR][r] = L;   /* per-step local scan */                        \
        }                                                                     \
        const int c  = w + ((J) << 4);      /* global chunk index   */        \
        const int s  = c & (RING_ - 1);                                       \
        const int sn = (c + 1) & (RING_ - 1);                                 \
        /* wait for carry into chunk c (flag value = c+1) */                  \
        while (vf[s] != c + 1) { }                                            \
        __threadfence_block();                                                \
        const float h = hbuf[s][lane];                                        \
        /* emit carry for chunk c+1 immediately */                            \
        hbuf[sn][lane] = fmaf(P, h, L);                                       \
        __threadfence_block();                                                \
        __syncwarp();                                                         \
        if (lane == 0) vf[sn] = c + 2;                                        \
        /* apply carry, store */                                              \
        _Pragma("unroll")                                                     \
        for (int r = 0; r < RC_; r++)                                         \
            __stcs(out + base + (size_t)r * D_, fmaf(A[CUR][r], h, X[CUR][r]));\
        base = nbase;                                                         \
    }

__global__ __launch_bounds__(TPB_, 1) void scan_kernel(const float* __restrict__ x,
                                                       const float* __restrict__ alpha,
                                                       float* __restrict__ out) {
    __shared__ float hbuf[RING_][32];   // carry value per ring slot
    __shared__ int   hflag[RING_];      // monotone counter: c+1 => carry into c ready

    const int tid  = threadIdx.x;
    const int lane = tid & 31;
    const int w    = tid >> 5;           // warp 0..15
    const int lg   = blockIdx.x;         // chain: b * 32 + dtile
    const int b    = lg >> 5;
    const int dt   = lg & 31;
    const int d    = dt * 32 + lane;

    volatile int* vf = hflag;

    // Init ring: carry into chunk 0 is zero, flag[0] = 1 (= c+1 for c=0).
    if (tid < RING_) hflag[tid] = (tid == 0) ? 1 : 0;
    if (tid < 32)    hbuf[0][tid] = 0.0f;
    __syncthreads();

    size_t base = ((size_t)b * S_ + (size_t)w * RC_) * (size_t)D_ + d;

    float A[2][RC_], X[2][RC_];

    // Preload this warp's first chunk.
#pragma unroll
    for (int r = 0; r < RC_; r++) A[0][r] = __ldcg(alpha + base + (size_t)r * D_);
#pragma unroll
    for (int r = 0; r < RC_; r++) X[0][r] = __ldcg(x + base + (size_t)r * D_);

#pragma unroll 1
    for (int j = 0; j < JITERS_; j += 2) {
        BODY(0, 1, j)
        BODY(1, 0, j + 1)
    }
}

extern "C" void kernel_launch(void* const* d_in, const int* in_sizes, int n_in,
                              void* d_out, int out_size) {
    const float* xp = (const float*)d_in[0];
    const float* ap = (const float*)d_in[1];
    float* op = (float*)d_out;

    scan_kernel<<<LG_, TPB_>>>(xp, ap, op);
}

// round 15
// speedup vs baseline: 1.1956x; 1.1811x over previous
#include <cuda_runtime.h>

// h_t = alpha_t * h_{t-1} + x_t over axis 1 of float32 [4, 8192, 1024].
// Persistent scan (R6, the proven structure): one block per (batch, 32-wide
// d-tile) chain = 128 blocks, 32 chunks of 256 rows, register double-buffered
// prefetch, one __syncthreads per chunk.
// R15: per-block phase stagger. All 128 blocks otherwise run identical
// self-timed loops and phase-lock, so the chip's DRAM demand arrives in
// aligned 12MB bursts each ~3400-cycle period (duty cycle ~79% = measured
// DRAM%). A deterministic clock64 spin of (lg & 15) * 256 cycles at entry
// spreads block phases across a full period so aggregate demand is smooth.

#define B_      4
#define S_      8192
#define D_      1024
#define R_      16                    // s-steps per thread per chunk
#define SUBS_   16                    // warps per block
#define TPB_    512
#define DTILE_  32                    // d-lanes per block
#define CHUNK_  (R_ * SUBS_)          // 256 s-steps per chunk
#define ITERS_  (S_ / CHUNK_)         // 32 chunks per chain
#define LG_     (B_ * (D_ / DTILE_))  // 128 chains = 128 blocks

// One chunk body. CUR/NXT are compile-time buffer indices (ping-pong).
// Prefetch LDGs for chunk K+1 are issued BEFORE the barrier/fold/stores of
// chunk K, so DRAM streams through the serial section.
#define BODY(CUR, NXT, K)                                                     \
    {                                                                         \
        const size_t nbase = base + (size_t)CHUNK_ * D_;                      \
        if ((K) + 1 < ITERS_) {                                               \
            _Pragma("unroll")                                                 \
            for (int r = 0; r < R_; r++)                                      \
                A[NXT][r] = __ldcg(alpha + nbase + (size_t)r * D_);           \
            _Pragma("unroll")                                                 \
            for (int r = 0; r < R_; r++)                                      \
                X[NXT][r] = __ldcg(x + nbase + (size_t)r * D_);               \
        }                                                                     \
        float P = 1.0f, L = 0.0f;                                             \
        _Pragma("unroll")                                                     \
        for (int r = 0; r < R_; r++) {                                        \
            L = fmaf(A[CUR][r], L, X[CUR][r]);                                \
            P = P * A[CUR][r];                                                \
            A[CUR][r] = P;   /* per-step cumprod  */                          \
            X[CUR][r] = L;   /* per-step local scan */                        \
        }                                                                     \
        sp[CUR][w][lane] = P;                                                 \
        sl[CUR][w][lane] = L;                                                 \
        __syncthreads();                                                      \
        /* every warp folds all 16 aggregates: h0 = prefix before own warp, */\
        /* acc = full fold -> next chunk's carry (identical in all warps).  */\
        float acc = cin, h0 = cin;                                            \
        _Pragma("unroll")                                                     \
        for (int w2 = 0; w2 < SUBS_; w2++) {                                  \
            if (w2 == w) h0 = acc;                                            \
            acc = fmaf(sp[CUR][w2][lane], acc, sl[CUR][w2][lane]);            \
        }                                                                     \
        cin = acc;                                                            \
        _Pragma("unroll")                                                     \
        for (int r = 0; r < R_; r++)                                          \
            __stcs(out + base + (size_t)r * D_, fmaf(A[CUR][r], h0, X[CUR][r]));\
        base = nbase;                                                         \
    }

__global__ __launch_bounds__(TPB_, 1) void scan_kernel(const float* __restrict__ x,
                                                       const float* __restrict__ alpha,
                                                       float* __restrict__ out) {
    // Double-buffered per-warp aggregates: one __syncthreads per chunk is
    // race-free (sync at k+1 separates read(k) from write(k+2), same buffer).
    __shared__ float sp[2][SUBS_][DTILE_];
    __shared__ float sl[2][SUBS_][DTILE_];

    const int lane = threadIdx.x & 31;
    const int w    = threadIdx.x >> 5;    // warp = s-subchunk within chunk
    const int lg   = blockIdx.x;          // chain: b * 32 + dtile
    const int b    = lg >> 5;
    const int dt   = lg & 31;
    const int d    = dt * DTILE_ + lane;

    // --- R15: deterministic phase stagger (~0..3840 cycles in 16 steps) ---
    {
        const long long delay = (long long)((lg & 15) * 256);
        const long long t0 = clock64();
        while (clock64() - t0 < delay) { }
    }
    __syncthreads();

    size_t base = ((size_t)b * S_ + (size_t)w * R_) * (size_t)D_ + d;

    float A[2][R_], X[2][R_];
    float cin = 0.0f;

    // Preload chunk 0.
#pragma unroll
    for (int r = 0; r < R_; r++) A[0][r] = __ldcg(alpha + base + (size_t)r * D_);
#pragma unroll
    for (int r = 0; r < R_; r++) X[0][r] = __ldcg(x + base + (size_t)r * D_);

#pragma unroll 1
    for (int k = 0; k < ITERS_; k += 2) {
        BODY(0, 1, k)
        BODY(1, 0, k + 1)
    }
}

extern "C" void kernel_launch(void* const* d_in, const int* in_sizes, int n_in,
                              void* d_out, int out_size) {
    const float* xp = (const float*)d_in[0];
    const float* ap = (const float*)d_in[1];
    float* op = (float*)d_out;

    scan_kernel<<<LG_, TPB_>>>(xp, ap, op);
}

// round 16
// speedup vs baseline: 1.2345x; 1.0325x over previous
#include <cuda_runtime.h>

// h_t = alpha_t * h_{t-1} + x_t over axis 1 of float32 [4, 8192, 1024].
// Persistent scan: one block per (batch, 32-wide d-tile) chain = 128 blocks.
// R16: cp.async (LDGSTS) smem staging pipeline. 4 stages x 128-row chunks,
// 3 chunks (96KB) continuously in flight via commit/wait groups — load
// production is decoupled from warp scheduling, barriers, and registers.
// Consumers LDS staged data (conflict-free), scan, and finalize chunk k-1
// (fold + STG) lagged one iteration so a single __syncthreads per chunk
// orders staged-data visibility, aggregate visibility, and stage reuse.

#define B_      4
#define S_      8192
#define D_      1024
#define TPB_    512                   // 16 warps
#define NW_     16
#define ROWS_   128                   // rows per chunk
#define RT_     8                     // rows per thread (= ROWS_/NW_)
#define ITERS_  (S_ / ROWS_)          // 64 chunks per chain
#define NSTG_   4                     // smem pipeline stages
#define LG_     (B_ * (D_ / 32))      // 128 chains = 128 blocks

// dynamic smem: stage[4][2][128][32] floats, then sp[2][16][32], sl[2][16][32]
#define STAGE_F (NSTG_ * 2 * ROWS_ * 32)      // 32768 floats
#define AGG_F   (2 * NW_ * 32)                // 1024 floats
#define SMEM_B  ((STAGE_F + 2 * AGG_F) * 4)   // 139264 bytes

static __device__ __forceinline__ void cp16(float* dst, const float* src) {
    unsigned int da = (unsigned int)__cvta_generic_to_shared(dst);
    asm volatile("cp.async.cg.shared.global [%0], [%1], 16;" :: "r"(da), "l"(src) : "memory");
}

__global__ __launch_bounds__(TPB_, 1) void scan_kernel(const float* __restrict__ x,
                                                       const float* __restrict__ alpha,
                                                       float* __restrict__ out) {
    extern __shared__ float sm[];
    float* stage = sm;                    // [stg][tensor][row][dlane]
    float* spb   = sm + STAGE_F;          // [2][16][32]
    float* slb   = spb + AGG_F;           // [2][16][32]

    const int tid  = threadIdx.x;
    const int lane = tid & 31;
    const int w    = tid >> 5;
    const int lg   = blockIdx.x;          // chain: b * 32 + dtile
    const int b    = lg >> 5;
    const int dt   = lg & 31;
    const int d0   = dt * 32;

    // ---- copy producer for chunk c (all threads; 4 x cp.async.cg each) ----
    #define ISSUE(c)                                                          \
    {                                                                         \
        const size_t eb = ((size_t)b * S_ + (size_t)(c) * ROWS_) * D_ + d0;   \
        float* stA = stage + (((c) & 3) * 2 + 0) * (ROWS_ * 32);              \
        float* stX = stage + (((c) & 3) * 2 + 1) * (ROWS_ * 32);              \
        _Pragma("unroll")                                                     \
        for (int i = 0; i < 2; i++) {                                         \
            const int u = tid + i * TPB_;      /* 16B unit: row=u>>3, col=u&7 */ \
            const size_t off = eb + (size_t)(u >> 3) * D_ + (size_t)(u & 7) * 4; \
            cp16(stA + u * 4, alpha + off);                                   \
            cp16(stX + u * 4, x + off);                                       \
        }                                                                     \
    }

    // Prologue: chunks 0,1,2 in flight (3 groups).
    ISSUE(0); asm volatile("cp.async.commit_group;" ::: "memory");
    ISSUE(1); asm volatile("cp.async.commit_group;" ::: "memory");
    ISSUE(2); asm volatile("cp.async.commit_group;" ::: "memory");

    float Ap[RT_], Xp[RT_];               // held scan results of chunk k-1
    float cin = 0.0f;
    size_t prev_sb = 0;

#pragma unroll 1
    for (int k = 0; k < ITERS_; k++) {
        // group k complete (k+1, k+2 still in flight)
        asm volatile("cp.async.wait_group 2;" ::: "memory");
        __syncthreads();   // chunk-k data visible; agg[k-1] visible; stage (k+3)&3 free

        if (k + 3 < ITERS_) ISSUE(k + 3);
        asm volatile("cp.async.commit_group;" ::: "memory");   // empty group at tail keeps counting exact

        // ---- consume chunk k: LDS + local scan ----
        const float* stA = stage + ((k & 3) * 2 + 0) * (ROWS_ * 32);
        const float* stX = stage + ((k & 3) * 2 + 1) * (ROWS_ * 32);
        float a[RT_], xv[RT_];
#pragma unroll
        for (int r = 0; r < RT_; r++) a[r]  = stA[(w * RT_ + r) * 32 + lane];
#pragma unroll
        for (int r = 0; r < RT_; r++) xv[r] = stX[(w * RT_ + r) * 32 + lane];

        float P = 1.0f, L = 0.0f;
#pragma unroll
        for (int r = 0; r < RT_; r++) {
            L = fmaf(a[r], L, xv[r]);
            P = P * a[r];
            a[r]  = P;    // per-row cumprod
            xv[r] = L;    // per-row local scan
        }
        spb[(k & 1) * (NW_ * 32) + w * 32 + lane] = P;
        slb[(k & 1) * (NW_ * 32) + w * 32 + lane] = L;

        // ---- finalize chunk k-1: fold its aggregates, apply carry, store ----
        if (k > 0) {
            const float* sp1 = spb + ((k - 1) & 1) * (NW_ * 32);
            const float* sl1 = slb + ((k - 1) & 1) * (NW_ * 32);
            float acc = cin, h0 = cin;
#pragma unroll
            for (int w2 = 0; w2 < NW_; w2++) {
                if (w2 == w) h0 = acc;
                acc = fmaf(sp1[w2 * 32 + lane], acc, sl1[w2 * 32 + lane]);
            }
            cin = acc;
#pragma unroll
            for (int r = 0; r < RT_; r++)
                __stcs(out + prev_sb + (size_t)r * D_, fmaf(Ap[r], h0, Xp[r]));
        }

        // rotate held registers / store base
#pragma unroll
        for (int r = 0; r < RT_; r++) { Ap[r] = a[r]; Xp[r] = xv[r]; }
        prev_sb = ((size_t)b * S_ + (size_t)k * ROWS_ + w * RT_) * D_ + d0 + lane;
    }

    // ---- epilogue: finalize last chunk ----
    __syncthreads();   // agg[ITERS-1] visibility
    {
        const float* sp1 = spb + ((ITERS_ - 1) & 1) * (NW_ * 32);
        const float* sl1 = slb + ((ITERS_ - 1) & 1) * (NW_ * 32);
        float acc = cin, h0 = cin;
#pragma unroll
        for (int w2 = 0; w2 < NW_; w2++) {
            if (w2 == w) h0 = acc;
            acc = fmaf(sp1[w2 * 32 + lane], acc, sl1[w2 * 32 + lane]);
        }
#pragma unroll
        for (int r = 0; r < RT_; r++)
            __stcs(out + prev_sb + (size_t)r * D_, fmaf(Ap[r], h0, Xp[r]));
    }
    #undef ISSUE
}

extern "C" void kernel_launch(void* const* d_in, const int* in_sizes, int n_in,
                              void* d_out, int out_size) {
    const float* xp = (const float*)d_in[0];
    const float* ap = (const float*)d_in[1];
    float* op = (float*)d_out;

    static int configured = 0;
    if (!configured) {
        cudaFuncSetAttribute(scan_kernel, cudaFuncAttributeMaxDynamicSharedMemorySize, SMEM_B);
        configured = 1;
    }
    scan_kernel<<<LG_, TPB_, SMEM_B>>>(xp, ap, op);
}